// round 15
// baseline (speedup 1.0000x reference)
#include <cuda_runtime.h>
#include <cuda_fp16.h>
#include <mma.h>
using namespace nvcuda;

#define D128 128
#define MAXN 50000
#define BK 32

// hgemm smem layout (dynamic)
#define CK 64
#define LDX 72
#define LDW 136
#define LDC 132
#define SMEM_XH 0
#define SMEM_WH 18432
#define SMEM_CF 35840
#define HGEMM_SMEM 103424

// ---------------- scratch ----------------
__device__ __align__(16) float  g_H1n[MAXN * D128];
__device__ __align__(16) __half g_A[MAXN * D128];
__device__ __align__(16) __half g_B[MAXN * D128];
__device__ __align__(16) float  g_S[MAXN * D128];
__device__ __align__(16) float  g_T[MAXN * D128];
__device__ __align__(16) float  g_deg[MAXN];
__device__ __align__(16) float  g_Wnc[D128 * D128];
__device__ __align__(16) float  g_Wec[D128 * D128];
__device__ __align__(16) float  g_cbias[D128];
__device__ __align__(16) float  g_evec[D128];
__device__ int g_idx64;

// ---------------- packed fp32x2 helpers ----------------
static __device__ __forceinline__ unsigned long long pack2(float x, float y) {
    unsigned long long r;
    asm("mov.b64 %0, {%1,%2};" : "=l"(r) : "f"(x), "f"(y));
    return r;
}
static __device__ __forceinline__ void fma2(unsigned long long& d,
                                            unsigned long long a,
                                            unsigned long long b) {
    asm("fma.rn.f32x2 %0, %1, %2, %0;" : "+l"(d) : "l"(a), "l"(b));
}
static __device__ __forceinline__ float2 unpack2(unsigned long long v) {
    float2 r;
    asm("mov.b64 {%0,%1}, %2;" : "=f"(r.x), "=f"(r.y) : "l"(v));
    return r;
}
static __device__ __forceinline__ unsigned h2u(__half2 h) {
    return *reinterpret_cast<unsigned*>(&h);
}
static __device__ __forceinline__ float2 u2f2(unsigned u) {
    __half2 h = *reinterpret_cast<__half2*>(&u);
    return __half22float2(h);
}

// ---------------- zero S/deg + (block 0) index dtype detect ----------------
__global__ void zero_detect_kernel(float4* __restrict__ S4, float* __restrict__ deg,
                                   long long nS4, int N,
                                   const unsigned int* __restrict__ w, int nwords)
{
    long long i = (long long)blockIdx.x * blockDim.x + threadIdx.x;
    if (i < nS4) S4[i] = make_float4(0.f, 0.f, 0.f, 0.f);
    long long j = i - nS4;
    if (j >= 0 && j < N) deg[j] = 0.f;

    if (blockIdx.x == 0) {
        __shared__ int any_nonzero;
        if (threadIdx.x == 0) any_nonzero = 0;
        __syncthreads();
        for (int t = threadIdx.x; t < nwords / 2; t += blockDim.x)
            if (w[2 * t + 1] != 0u) any_nonzero = 1;
        __syncthreads();
        if (threadIdx.x == 0) g_idx64 = any_nonzero ? 0 : 1;
    }
}

// ---------------- wmma inner: Cf = half(Xf32[n0:n0+128,:]) @ half(Wf) ----------------
// X loader reads fp32 and converts in-flight (same rounding as a separate convert pass).
__device__ __forceinline__ void wmma_pass_f32(
    const float* __restrict__ Xf, const float* __restrict__ Wf,
    int n0, int N, int tid, __half* Xs, __half* Ws, float* Cf)
{
    int w = tid >> 5;
    int warpM = w >> 1, warpN = w & 1;

    wmma::fragment<wmma::accumulator, 16, 16, 16, float> acc[2][4];
    #pragma unroll
    for (int i = 0; i < 2; i++)
        #pragma unroll
        for (int j = 0; j < 4; j++) wmma::fill_fragment(acc[i][j], 0.f);

    for (int kk = 0; kk < 128; kk += CK) {
        __syncthreads();
        // X tile: 128 rows x CK halfs; each chunk = 8 halfs = two float4 source loads
        #pragma unroll
        for (int it = 0; it < 4; it++) {
            int idx = tid + it * 256;
            int row = idx >> 3, cq = idx & 7;
            int gr = n0 + row; if (gr > N - 1) gr = N - 1;
            const float* sp = Xf + (size_t)gr * 128 + kk + cq * 8;
            float4 v0 = *(const float4*)(sp);
            float4 v1 = *(const float4*)(sp + 4);
            uint4 u;
            u.x = h2u(__floats2half2_rn(v0.x, v0.y));
            u.y = h2u(__floats2half2_rn(v0.z, v0.w));
            u.z = h2u(__floats2half2_rn(v1.x, v1.y));
            u.w = h2u(__floats2half2_rn(v1.z, v1.w));
            *(uint4*)(Xs + row * LDX + cq * 8) = u;
        }
        #pragma unroll
        for (int it = 0; it < 8; it++) {
            int idx = tid + it * 256;
            int kr = idx >> 5, cq = idx & 31;
            float4 v = *(const float4*)(Wf + (size_t)(kk + kr) * 128 + cq * 4);
            uint2 u;
            u.x = h2u(__floats2half2_rn(v.x, v.y));
            u.y = h2u(__floats2half2_rn(v.z, v.w));
            *(uint2*)(Ws + (size_t)kr * LDW + cq * 4) = u;
        }
        __syncthreads();
        #pragma unroll
        for (int ks = 0; ks < CK / 16; ks++) {
            wmma::fragment<wmma::matrix_a, 16, 16, 16, __half, wmma::row_major> af[2];
            wmma::fragment<wmma::matrix_b, 16, 16, 16, __half, wmma::row_major> bf[4];
            #pragma unroll
            for (int i = 0; i < 2; i++)
                wmma::load_matrix_sync(af[i], Xs + (warpM * 32 + i * 16) * LDX + ks * 16, LDX);
            #pragma unroll
            for (int j = 0; j < 4; j++)
                wmma::load_matrix_sync(bf[j], Ws + ks * 16 * LDW + warpN * 64 + j * 16, LDW);
            #pragma unroll
            for (int i = 0; i < 2; i++)
                #pragma unroll
                for (int j = 0; j < 4; j++)
                    wmma::mma_sync(acc[i][j], af[i], bf[j], acc[i][j]);
        }
    }

    #pragma unroll
    for (int i = 0; i < 2; i++)
        #pragma unroll
        for (int j = 0; j < 4; j++)
            wmma::store_matrix_sync(Cf + (warpM * 32 + i * 16) * LDC + warpN * 64 + j * 16,
                                    acc[i][j], LDC, wmma::mem_row_major);
    __syncthreads();
}

// ---------------- wmma GEMM for H/A/B (ybase splits launches) ----------------
__global__ __launch_bounds__(256) void hgemm_hab_kernel(
    const float* __restrict__ x,
    const float* __restrict__ node_w1, const float* __restrict__ edge_w1,
    const float* __restrict__ bias, const float* __restrict__ g,
    const float* __restrict__ be,
    float* __restrict__ H, __half* __restrict__ A, __half* __restrict__ B,
    int N, int ybase)
{
    extern __shared__ char ds[];
    __half* Xs = (__half*)(ds + SMEM_XH);
    __half* Ws = (__half*)(ds + SMEM_WH);
    float*  Cf = (float*)(ds + SMEM_CF);

    int tid = threadIdx.x;
    int y = blockIdx.y + ybase;
    int n0 = blockIdx.x * 128;
    const float* Wf = (y == 0) ? node_w1 : (y == 1 ? edge_w1 : edge_w1 + 128 * 128);

    wmma_pass_f32(x, Wf, n0, N, tid, Xs, Ws, Cf);

    int tx = tid & 15, ty = tid >> 4;
    if (y == 0) {
        float4 bi0 = *(const float4*)(bias + tx * 4);
        float4 bi1 = *(const float4*)(bias + 64 + tx * 4);
        float4 gg0 = *(const float4*)(g + tx * 4);
        float4 gg1 = *(const float4*)(g + 64 + tx * 4);
        float4 ee0 = *(const float4*)(be + tx * 4);
        float4 ee1 = *(const float4*)(be + 64 + tx * 4);
        #pragma unroll
        for (int i = 0; i < 8; i++) {
            int row = (i < 4) ? (ty * 4 + i) : (64 + ty * 4 + (i - 4));
            int gr = n0 + row;
            const float* cr = Cf + row * LDC;
            float v[8] = { cr[tx*4+0] + bi0.x, cr[tx*4+1] + bi0.y,
                           cr[tx*4+2] + bi0.z, cr[tx*4+3] + bi0.w,
                           cr[64+tx*4+0] + bi1.x, cr[64+tx*4+1] + bi1.y,
                           cr[64+tx*4+2] + bi1.z, cr[64+tx*4+3] + bi1.w };
            float s = 0.f, ss = 0.f;
            #pragma unroll
            for (int j = 0; j < 8; j++) { s += v[j]; ss += v[j] * v[j]; }
            #pragma unroll
            for (int o = 8; o; o >>= 1) {
                s  += __shfl_xor_sync(0xffffffffu, s,  o);
                ss += __shfl_xor_sync(0xffffffffu, ss, o);
            }
            float mean = s * (1.0f / 128.0f);
            float var  = ss * (1.0f / 128.0f) - mean * mean;
            float rs   = rsqrtf(var + 1e-5f);
            float o0 = fmaxf(0.f, (v[0] - mean) * rs * gg0.x + ee0.x);
            float o1 = fmaxf(0.f, (v[1] - mean) * rs * gg0.y + ee0.y);
            float o2 = fmaxf(0.f, (v[2] - mean) * rs * gg0.z + ee0.z);
            float o3 = fmaxf(0.f, (v[3] - mean) * rs * gg0.w + ee0.w);
            float o4 = fmaxf(0.f, (v[4] - mean) * rs * gg1.x + ee1.x);
            float o5 = fmaxf(0.f, (v[5] - mean) * rs * gg1.y + ee1.y);
            float o6 = fmaxf(0.f, (v[6] - mean) * rs * gg1.z + ee1.z);
            float o7 = fmaxf(0.f, (v[7] - mean) * rs * gg1.w + ee1.w);
            if (gr < N) {
                *(float4*)(H + (size_t)gr * 128 + tx * 4)      = make_float4(o0, o1, o2, o3);
                *(float4*)(H + (size_t)gr * 128 + 64 + tx * 4) = make_float4(o4, o5, o6, o7);
            }
        }
    } else {
        __half* Yh = (y == 1) ? A : B;
        #pragma unroll
        for (int i = 0; i < 8; i++) {
            int row = (i < 4) ? (ty * 4 + i) : (64 + ty * 4 + (i - 4));
            int gr = n0 + row;
            if (gr < N) {
                const float* cr = Cf + row * LDC;
                uint2 u0, u1;
                u0.x = h2u(__floats2half2_rn(cr[tx*4+0], cr[tx*4+1]));
                u0.y = h2u(__floats2half2_rn(cr[tx*4+2], cr[tx*4+3]));
                u1.x = h2u(__floats2half2_rn(cr[64+tx*4+0], cr[64+tx*4+1]));
                u1.y = h2u(__floats2half2_rn(cr[64+tx*4+2], cr[64+tx*4+3]));
                *(uint2*)(Yh + (size_t)gr * 128 + tx * 4)      = u0;
                *(uint2*)(Yh + (size_t)gr * 128 + 64 + tx * 4) = u1;
            }
        }
    }
}

// ---------------- wmma final: out = LN(S@Wec + T + x + cbias + deg*evec) ----------------
__global__ __launch_bounds__(256) void final_wmma_kernel(
    const float* __restrict__ S, const float* __restrict__ T,
    const float* __restrict__ x, const float* __restrict__ deg,
    const float* __restrict__ lng, const float* __restrict__ lnb,
    float* __restrict__ Y, int N)
{
    extern __shared__ char ds[];
    __half* Xs = (__half*)(ds + SMEM_XH);
    __half* Ws = (__half*)(ds + SMEM_WH);
    float*  Cf = (float*)(ds + SMEM_CF);

    int tid = threadIdx.x;
    int n0 = blockIdx.x * 128;

    wmma_pass_f32(S, g_Wec, n0, N, tid, Xs, Ws, Cf);

    int tx = tid & 15, ty = tid >> 4;
    float4 cb0 = *(const float4*)(g_cbias + tx * 4);
    float4 cb1 = *(const float4*)(g_cbias + 64 + tx * 4);
    float4 ev0 = *(const float4*)(g_evec + tx * 4);
    float4 ev1 = *(const float4*)(g_evec + 64 + tx * 4);
    float4 gg0 = *(const float4*)(lng + tx * 4);
    float4 gg1 = *(const float4*)(lng + 64 + tx * 4);
    float4 bb0 = *(const float4*)(lnb + tx * 4);
    float4 bb1 = *(const float4*)(lnb + 64 + tx * 4);

    #pragma unroll
    for (int i = 0; i < 8; i++) {
        int row = (i < 4) ? (ty * 4 + i) : (64 + ty * 4 + (i - 4));
        int gr = n0 + row;
        int gl = (gr > N - 1) ? (N - 1) : gr;
        float d = deg[gl];
        float4 xr0 = *(const float4*)(x + (size_t)gl * 128 + tx * 4);
        float4 xr1 = *(const float4*)(x + (size_t)gl * 128 + 64 + tx * 4);
        float4 tr0 = *(const float4*)(T + (size_t)gl * 128 + tx * 4);
        float4 tr1 = *(const float4*)(T + (size_t)gl * 128 + 64 + tx * 4);
        const float* cr = Cf + row * LDC;
        float v[8];
        v[0] = cr[tx*4+0] + tr0.x + xr0.x + cb0.x + d * ev0.x;
        v[1] = cr[tx*4+1] + tr0.y + xr0.y + cb0.y + d * ev0.y;
        v[2] = cr[tx*4+2] + tr0.z + xr0.z + cb0.z + d * ev0.z;
        v[3] = cr[tx*4+3] + tr0.w + xr0.w + cb0.w + d * ev0.w;
        v[4] = cr[64+tx*4+0] + tr1.x + xr1.x + cb1.x + d * ev1.x;
        v[5] = cr[64+tx*4+1] + tr1.y + xr1.y + cb1.y + d * ev1.y;
        v[6] = cr[64+tx*4+2] + tr1.z + xr1.z + cb1.z + d * ev1.z;
        v[7] = cr[64+tx*4+3] + tr1.w + xr1.w + cb1.w + d * ev1.w;
        float s = 0.f, ss = 0.f;
        #pragma unroll
        for (int j = 0; j < 8; j++) { s += v[j]; ss += v[j] * v[j]; }
        #pragma unroll
        for (int o = 8; o; o >>= 1) {
            s  += __shfl_xor_sync(0xffffffffu, s,  o);
            ss += __shfl_xor_sync(0xffffffffu, ss, o);
        }
        float mean = s * (1.0f / 128.0f);
        float var  = ss * (1.0f / 128.0f) - mean * mean;
        float rs   = rsqrtf(var + 1e-5f);
        float o0 = (v[0] - mean) * rs * gg0.x + bb0.x;
        float o1 = (v[1] - mean) * rs * gg0.y + bb0.y;
        float o2 = (v[2] - mean) * rs * gg0.z + bb0.z;
        float o3 = (v[3] - mean) * rs * gg0.w + bb0.w;
        float o4 = (v[4] - mean) * rs * gg1.x + bb1.x;
        float o5 = (v[5] - mean) * rs * gg1.y + bb1.y;
        float o6 = (v[6] - mean) * rs * gg1.z + bb1.z;
        float o7 = (v[7] - mean) * rs * gg1.w + bb1.w;
        if (gr < N) {
            *(float4*)(Y + (size_t)gr * 128 + tx * 4)      = make_float4(o0, o1, o2, o3);
            *(float4*)(Y + (size_t)gr * 128 + 64 + tx * 4) = make_float4(o4, o5, o6, o7);
        }
    }
}

// ---------------- shared FFMA GEMM inner pass (for T + prep) ----------------
__device__ __forceinline__ void gemm_pass(
    const float* __restrict__ X, const float* __restrict__ W,
    int n0, int N, int tid, int tx, int ty,
    float* Xs2, float* Ws, unsigned long long (&acc)[8][4])
{
    for (int kk = 0; kk < 128; kk += BK) {
        __syncthreads();
        #pragma unroll
        for (int i = 0; i < 4; i++) {
            int idx = tid + i * 256;
            int row = idx >> 3, q = idx & 7;
            int gr = n0 + row; if (gr > N - 1) gr = N - 1;
            float4 v = *(const float4*)(X + (size_t)gr * 128 + kk + q * 4);
            float* s = Xs2 + row * 64 + q * 8;
            *(float4*)(s)     = make_float4(v.x, v.x, v.y, v.y);
            *(float4*)(s + 4) = make_float4(v.z, v.z, v.w, v.w);
        }
        #pragma unroll
        for (int i = 0; i < 4; i++) {
            int idx = tid + i * 256;
            int kr = idx >> 5, cq = idx & 31;
            float4 v = *(const float4*)(W + (size_t)(kk + kr) * 128 + cq * 4);
            *(float4*)(Ws + kr * 128 + cq * 4) = v;
        }
        __syncthreads();
        #pragma unroll
        for (int k = 0; k < BK; k++) {
            float4 b0 = *(const float4*)(Ws + k * 128 + tx * 4);
            float4 b1 = *(const float4*)(Ws + k * 128 + 64 + tx * 4);
            unsigned long long bp[4];
            bp[0] = pack2(b0.x, b0.y); bp[1] = pack2(b0.z, b0.w);
            bp[2] = pack2(b1.x, b1.y); bp[3] = pack2(b1.z, b1.w);
            #pragma unroll
            for (int i = 0; i < 8; i++) {
                int row = (i < 4) ? (ty * 4 + i) : (64 + ty * 4 + (i - 4));
                unsigned long long a2 =
                    *(const unsigned long long*)(Xs2 + row * 64 + k * 2);
                fma2(acc[i][0], a2, bp[0]);
                fma2(acc[i][1], a2, bp[1]);
                fma2(acc[i][2], a2, bp[2]);
                fma2(acc[i][3], a2, bp[3]);
            }
        }
    }
}

// ---------------- T = H @ Wnc ----------------
__global__ __launch_bounds__(256, 2) void gemm_t_kernel(
    const float* __restrict__ H, float* __restrict__ T, int N)
{
    __shared__ float Xs2[128 * 64];
    __shared__ float Ws[BK * 128];
    int tid = threadIdx.x, tx = tid & 15, ty = tid >> 4;
    int n0 = blockIdx.x * 128;
    unsigned long long acc[8][4];
    #pragma unroll
    for (int i = 0; i < 8; i++)
        #pragma unroll
        for (int p = 0; p < 4; p++) acc[i][p] = 0ULL;

    gemm_pass(H, g_Wnc, n0, N, tid, tx, ty, Xs2, Ws, acc);

    #pragma unroll
    for (int i = 0; i < 8; i++) {
        int row = (i < 4) ? (ty * 4 + i) : (64 + ty * 4 + (i - 4));
        int gr = n0 + row;
        if (gr < N) {
            float2 f0 = unpack2(acc[i][0]), f1 = unpack2(acc[i][1]);
            float2 f2 = unpack2(acc[i][2]), f3 = unpack2(acc[i][3]);
            *(float4*)(T + (size_t)gr * 128 + tx * 4)      = make_float4(f0.x, f0.y, f1.x, f1.y);
            *(float4*)(T + (size_t)gr * 128 + 64 + tx * 4) = make_float4(f2.x, f2.y, f3.x, f3.y);
        }
    }
}

// ---------------- edge kernel (R12 low-reg ILP-2) ----------------
__global__ __launch_bounds__(256, 5) void edge_kernel(
    const __half* __restrict__ A, const __half* __restrict__ B,
    const float* __restrict__ ea, const void* __restrict__ ei_raw,
    const float* __restrict__ W5, const float* __restrict__ eb1,
    const float* __restrict__ g1, const float* __restrict__ be1,
    float* __restrict__ S, float* __restrict__ deg, int E, int N)
{
    __shared__ float sW5[5 * 128];
    __shared__ float sb[128], sg[128], sbe[128];
    int tid = threadIdx.x;
    for (int i = tid; i < 5 * 128; i += 256) sW5[i] = W5[i];
    if (tid < 128) { sb[tid] = eb1[tid]; sg[tid] = g1[tid]; sbe[tid] = be1[tid]; }
    __syncthreads();

    int lane = tid & 31;
    int gw = (blockIdx.x * 256 + tid) >> 5;
    int nw = (gridDim.x * 256) >> 5;
    int idx64 = g_idx64;
    int c = lane * 4;

    for (long long e0 = 2LL * gw; e0 < E; e0 += 2LL * nw) {
        long long e1 = e0 + 1;
        bool valid1 = (e1 < E);

        int src0, dst0, src1, dst1;
        if (idx64) {
            const long long* ei = (const long long*)ei_raw;
            src0 = (int)ei[e0];
            dst0 = (int)ei[(long long)E + e0];
            src1 = valid1 ? (int)ei[e1] : src0;
            dst1 = valid1 ? (int)ei[(long long)E + e1] : dst0;
        } else {
            const int* ei = (const int*)ei_raw;
            src0 = ei[e0];
            dst0 = ei[(long long)E + e0];
            src1 = valid1 ? ei[e1] : src0;
            dst1 = valid1 ? ei[(long long)E + e1] : dst0;
        }
        src0 = min(max(src0, 0), N - 1); dst0 = min(max(dst0, 0), N - 1);
        src1 = min(max(src1, 0), N - 1); dst1 = min(max(dst1, 0), N - 1);

        uint2 ra0 = __ldg((const uint2*)(A + (size_t)src0 * 128 + c));
        uint2 rb0 = __ldg((const uint2*)(B + (size_t)dst0 * 128 + c));
        uint2 ra1 = __ldg((const uint2*)(A + (size_t)src1 * 128 + c));
        uint2 rb1 = __ldg((const uint2*)(B + (size_t)dst1 * 128 + c));

        const float* eap0 = ea + e0 * 5;
        const float* eap1 = ea + (valid1 ? e1 : e0) * 5;
        float e00 = eap0[0], e01 = eap0[1], e02 = eap0[2], e03 = eap0[3], e04 = eap0[4];
        float e10 = eap1[0], e11 = eap1[1], e12 = eap1[2], e13 = eap1[3], e14 = eap1[4];

        float4 w0 = *(const float4*)(sW5 + 0 * 128 + c);
        float4 w1 = *(const float4*)(sW5 + 1 * 128 + c);
        float4 w2 = *(const float4*)(sW5 + 2 * 128 + c);
        float4 w3 = *(const float4*)(sW5 + 3 * 128 + c);
        float4 w4 = *(const float4*)(sW5 + 4 * 128 + c);
        float4 sb4 = *(const float4*)(sb + c);

        float b00 = sb4.x + e00 * w0.x + e01 * w1.x + e02 * w2.x + e03 * w3.x + e04 * w4.x;
        float b01 = sb4.y + e00 * w0.y + e01 * w1.y + e02 * w2.y + e03 * w3.y + e04 * w4.y;
        float b02 = sb4.z + e00 * w0.z + e01 * w1.z + e02 * w2.z + e03 * w3.z + e04 * w4.z;
        float b03 = sb4.w + e00 * w0.w + e01 * w1.w + e02 * w2.w + e03 * w3.w + e04 * w4.w;
        float b10 = sb4.x + e10 * w0.x + e11 * w1.x + e12 * w2.x + e13 * w3.x + e14 * w4.x;
        float b11 = sb4.y + e10 * w0.y + e11 * w1.y + e12 * w2.y + e13 * w3.y + e14 * w4.y;
        float b12 = sb4.z + e10 * w0.z + e11 * w1.z + e12 * w2.z + e13 * w3.z + e14 * w4.z;
        float b13 = sb4.w + e10 * w0.w + e11 * w1.w + e12 * w2.w + e13 * w3.w + e14 * w4.w;

        float2 a0lo = u2f2(ra0.x), a0hi = u2f2(ra0.y);
        float2 b0lo = u2f2(rb0.x), b0hi = u2f2(rb0.y);
        float2 a1lo = u2f2(ra1.x), a1hi = u2f2(ra1.y);
        float2 b1lo = u2f2(rb1.x), b1hi = u2f2(rb1.y);

        float p00 = a0lo.x + b0lo.x + b00;
        float p01 = a0lo.y + b0lo.y + b01;
        float p02 = a0hi.x + b0hi.x + b02;
        float p03 = a0hi.y + b0hi.y + b03;
        float p10 = a1lo.x + b1lo.x + b10;
        float p11 = a1lo.y + b1lo.y + b11;
        float p12 = a1hi.x + b1hi.x + b12;
        float p13 = a1hi.y + b1hi.y + b13;

        float s0 = p00 + p01 + p02 + p03;
        float q0 = p00 * p00 + p01 * p01 + p02 * p02 + p03 * p03;
        float s1 = p10 + p11 + p12 + p13;
        float q1 = p10 * p10 + p11 * p11 + p12 * p12 + p13 * p13;
        #pragma unroll
        for (int o = 16; o; o >>= 1) {
            s0 += __shfl_xor_sync(0xffffffffu, s0, o);
            q0 += __shfl_xor_sync(0xffffffffu, q0, o);
            s1 += __shfl_xor_sync(0xffffffffu, s1, o);
            q1 += __shfl_xor_sync(0xffffffffu, q1, o);
        }
        float mean0 = s0 * (1.0f / 128.0f);
        float rs0   = rsqrtf(q0 * (1.0f / 128.0f) - mean0 * mean0 + 1e-5f);
        float mean1 = s1 * (1.0f / 128.0f);
        float rs1   = rsqrtf(q1 * (1.0f / 128.0f) - mean1 * mean1 + 1e-5f);

        float4 sg4 = *(const float4*)(sg + c);
        float4 se4 = *(const float4*)(sbe + c);

        float v00 = fmaxf(0.f, (p00 - mean0) * rs0 * sg4.x + se4.x);
        float v01 = fmaxf(0.f, (p01 - mean0) * rs0 * sg4.y + se4.y);
        float v02 = fmaxf(0.f, (p02 - mean0) * rs0 * sg4.z + se4.z);
        float v03 = fmaxf(0.f, (p03 - mean0) * rs0 * sg4.w + se4.w);

        float* dp0 = S + (size_t)dst0 * 128 + c;
        asm volatile("red.global.add.v4.f32 [%0], {%1,%2,%3,%4};"
                     :: "l"(dp0), "f"(v00), "f"(v01), "f"(v02), "f"(v03) : "memory");

        if (valid1) {
            float v10 = fmaxf(0.f, (p10 - mean1) * rs1 * sg4.x + se4.x);
            float v11 = fmaxf(0.f, (p11 - mean1) * rs1 * sg4.y + se4.y);
            float v12 = fmaxf(0.f, (p12 - mean1) * rs1 * sg4.z + se4.z);
            float v13 = fmaxf(0.f, (p13 - mean1) * rs1 * sg4.w + se4.w);
            float* dp1 = S + (size_t)dst1 * 128 + c;
            asm volatile("red.global.add.v4.f32 [%0], {%1,%2,%3,%4};"
                         :: "l"(dp1), "f"(v10), "f"(v11), "f"(v12), "f"(v13) : "memory");
        }
        if (lane == 0) atomicAdd(deg + dst0, 1.0f);
        if (lane == 1 && valid1) atomicAdd(deg + dst1, 1.0f);
    }
}

// ---------------- prep kernel ----------------
__global__ __launch_bounds__(256, 2) void prep_kernel(
    const float* __restrict__ w2n, const float* __restrict__ w2e,
    const float* __restrict__ U,
    const float* __restrict__ bn2, const float* __restrict__ be2,
    const float* __restrict__ ub,
    float* __restrict__ Wnc, float* __restrict__ Wec,
    float* __restrict__ cb, float* __restrict__ ev)
{
    __shared__ float Xs2[128 * 64];
    __shared__ float Ws[BK * 128];
    int tid = threadIdx.x, tx = tid & 15, ty = tid >> 4;
    int y = blockIdx.y;

    if (y == 2) {
        int j = tid & 127, h = tid >> 7;
        float a = 0.f, b = 0.f;
        int m0 = h * 64;
        #pragma unroll 16
        for (int m = m0; m < m0 + 64; m++) {
            a += bn2[m] * U[m * 128 + j];
            b += be2[m] * U[(128 + m) * 128 + j];
        }
        Xs2[tid] = a;
        Xs2[512 + tid] = b;
        __syncthreads();
        if (h == 0) {
            cb[j] = Xs2[j] + Xs2[128 + j] + ub[j];
            ev[j] = Xs2[512 + j] + Xs2[640 + j];
        }
        return;
    }

    const float* X = y ? w2e : w2n;
    const float* W = y ? (U + 128 * 128) : U;
    float* out = y ? Wec : Wnc;

    unsigned long long acc[8][4];
    #pragma unroll
    for (int i = 0; i < 8; i++)
        #pragma unroll
        for (int p = 0; p < 4; p++) acc[i][p] = 0ULL;

    gemm_pass(X, W, 0, 128, tid, tx, ty, Xs2, Ws, acc);

    #pragma unroll
    for (int i = 0; i < 8; i++) {
        int row = (i < 4) ? (ty * 4 + i) : (64 + ty * 4 + (i - 4));
        float2 f0 = unpack2(acc[i][0]), f1 = unpack2(acc[i][1]);
        float2 f2 = unpack2(acc[i][2]), f3 = unpack2(acc[i][3]);
        *(float4*)(out + (size_t)row * 128 + tx * 4)      = make_float4(f0.x, f0.y, f1.x, f1.y);
        *(float4*)(out + (size_t)row * 128 + 64 + tx * 4) = make_float4(f2.x, f2.y, f3.x, f3.y);
    }
}

// ---------------- launch ----------------
extern "C" void kernel_launch(void* const* d_in, const int* in_sizes, int n_in,
                              void* d_out, int out_size)
{
    const float* x         = (const float*)d_in[0];
    const float* edge_attr = (const float*)d_in[1];
    const float* node_w1   = (const float*)d_in[3];
    const float* node_b1   = (const float*)d_in[4];
    const float* node_g1   = (const float*)d_in[5];
    const float* node_be1  = (const float*)d_in[6];
    const float* node_w2   = (const float*)d_in[7];
    const float* node_b2   = (const float*)d_in[8];
    const float* edge_w1   = (const float*)d_in[9];
    const float* edge_b1   = (const float*)d_in[10];
    const float* edge_g1   = (const float*)d_in[11];
    const float* edge_be1  = (const float*)d_in[12];
    const float* edge_w2   = (const float*)d_in[13];
    const float* edge_b2   = (const float*)d_in[14];
    const float* upd_w     = (const float*)d_in[15];
    const float* upd_b     = (const float*)d_in[16];
    const float* ln_g      = (const float*)d_in[17];
    const float* ln_b      = (const float*)d_in[18];
    const void*  ei        = d_in[19];
    float* out = (float*)d_out;

    int N = in_sizes[0] / 128;
    int E = in_sizes[19] / 2;

    float *pH, *pS, *pT, *pdeg, *pWnc, *pWec, *pcb, *pev;
    __half *pA, *pB;
    cudaGetSymbolAddress((void**)&pH,   g_H1n);
    cudaGetSymbolAddress((void**)&pA,   g_A);
    cudaGetSymbolAddress((void**)&pB,   g_B);
    cudaGetSymbolAddress((void**)&pS,   g_S);
    cudaGetSymbolAddress((void**)&pT,   g_T);
    cudaGetSymbolAddress((void**)&pdeg, g_deg);
    cudaGetSymbolAddress((void**)&pWnc, g_Wnc);
    cudaGetSymbolAddress((void**)&pWec, g_Wec);
    cudaGetSymbolAddress((void**)&pcb,  g_cbias);
    cudaGetSymbolAddress((void**)&pev,  g_evec);

    static cudaStream_t s1 = 0;
    static cudaEvent_t eFork = 0, eZero = 0, eAB = 0, eJoin = 0;
    static bool attrSet = false;
    if (!s1) cudaStreamCreateWithFlags(&s1, cudaStreamNonBlocking);
    if (!eFork) cudaEventCreateWithFlags(&eFork, cudaEventDisableTiming);
    if (!eZero) cudaEventCreateWithFlags(&eZero, cudaEventDisableTiming);
    if (!eAB) cudaEventCreateWithFlags(&eAB, cudaEventDisableTiming);
    if (!eJoin) cudaEventCreateWithFlags(&eJoin, cudaEventDisableTiming);
    if (!attrSet) {
        cudaFuncSetAttribute(hgemm_hab_kernel,
                             cudaFuncAttributeMaxDynamicSharedMemorySize, HGEMM_SMEM);
        cudaFuncSetAttribute(final_wmma_kernel,
                             cudaFuncAttributeMaxDynamicSharedMemorySize, HGEMM_SMEM);
        attrSet = true;
    }

    cudaStream_t s0 = cudaStreamLegacy;
    {
        cudaStreamCaptureStatus st = cudaStreamCaptureStatusNone;
        if (cudaStreamIsCapturing(cudaStreamLegacy, &st) == cudaSuccess &&
            st == cudaStreamCaptureStatusActive) {
            s0 = cudaStreamLegacy;
        } else {
            cudaStreamCaptureStatus st2 = cudaStreamCaptureStatusNone;
            if (cudaStreamIsCapturing(cudaStreamPerThread, &st2) == cudaSuccess &&
                st2 == cudaStreamCaptureStatusActive) {
                s0 = cudaStreamPerThread;
            }
        }
    }

    int gb = (N + 127) / 128;
    int nwords = 2 * E; if (nwords > 1024) nwords = 1024;
    long long nS4 = (long long)N * 32;
    long long ztot = nS4 + N;

    // fork
    cudaEventRecord(eFork, s0);
    cudaStreamWaitEvent(s1, eFork, 0);

    // s0 #1: A,B via wmma (fp32-x in-loader convert); edge only needs these
    hgemm_hab_kernel<<<dim3(gb, 2), 256, HGEMM_SMEM, s0>>>(
        x, node_w1, edge_w1, node_b1, node_g1, node_be1, pH, pA, pB, N, /*ybase=*/1);
    cudaEventRecord(eAB, s0);

    // s1: zero S/deg + dtype detect
    zero_detect_kernel<<<(unsigned)((ztot + 255) / 256), 256, 0, s1>>>(
        (float4*)pS, pdeg, nS4, N, (const unsigned int*)ei, nwords);
    cudaEventRecord(eZero, s1);

    // s1: prep (weight folding)
    prep_kernel<<<dim3(1, 3), 256, 0, s1>>>(node_w2, edge_w2, upd_w,
                                            node_b2, edge_b2, upd_b,
                                            pWnc, pWec, pcb, pev);

    // s1: H via wmma (after AB so it doesn't contend with the critical head)
    cudaStreamWaitEvent(s1, eAB, 0);
    hgemm_hab_kernel<<<dim3(gb, 1), 256, HGEMM_SMEM, s1>>>(
        x, node_w1, edge_w1, node_b1, node_g1, node_be1, pH, pA, pB, N, /*ybase=*/0);

    // s1: T = H @ Wnc
    gemm_t_kernel<<<gb, 256, 0, s1>>>(pH, pT, N);

    // s0: edge pipeline (waits zero)
    cudaStreamWaitEvent(s0, eZero, 0);
    edge_kernel<<<740, 256, 0, s0>>>(pA, pB, edge_attr, ei,
                                     edge_w1 + 256 * 128, edge_b1, edge_g1, edge_be1,
                                     pS, pdeg, E, N);

    // join
    cudaEventRecord(eJoin, s1);
    cudaStreamWaitEvent(s0, eJoin, 0);

    // s0: final via wmma (S fp32 converted in-loader)
    final_wmma_kernel<<<gb, 256, HGEMM_SMEM, s0>>>(pS, pT, x, pdeg, ln_g, ln_b, out, N);
}

// round 16
// speedup vs baseline: 1.1671x; 1.1671x over previous
#include <cuda_runtime.h>
#include <cuda_fp16.h>
#include <mma.h>
using namespace nvcuda;

#define D128 128
#define MAXN 50000
#define BK 32

// hgemm smem layout (dynamic)
#define CK 64
#define LDX 72
#define LDW 136
#define LDC 132
#define SMEM_XH 0
#define SMEM_WH 18432
#define SMEM_CF 35840
#define HGEMM_SMEM 103424

// ---------------- scratch ----------------
__device__ __align__(16) __half g_xh[MAXN * D128];
__device__ __align__(16) __half g_Hh[MAXN * D128];  // relu(LN(x@w1+b1)) in fp16
__device__ __align__(16) __half g_A[MAXN * D128];
__device__ __align__(16) __half g_B[MAXN * D128];
__device__ __align__(16) float  g_S[MAXN * D128];
__device__ __align__(16) float  g_T[MAXN * D128];
__device__ __align__(16) float  g_deg[MAXN];
__device__ __align__(16) float  g_Wnc[D128 * D128];
__device__ __align__(16) float  g_Wec[D128 * D128];
__device__ __align__(16) float  g_cbias[D128];
__device__ __align__(16) float  g_evec[D128];
__device__ int g_idx64;

// ---------------- packed fp32x2 helpers ----------------
static __device__ __forceinline__ unsigned long long pack2(float x, float y) {
    unsigned long long r;
    asm("mov.b64 %0, {%1,%2};" : "=l"(r) : "f"(x), "f"(y));
    return r;
}
static __device__ __forceinline__ void fma2(unsigned long long& d,
                                            unsigned long long a,
                                            unsigned long long b) {
    asm("fma.rn.f32x2 %0, %1, %2, %0;" : "+l"(d) : "l"(a), "l"(b));
}
static __device__ __forceinline__ float2 unpack2(unsigned long long v) {
    float2 r;
    asm("mov.b64 {%0,%1}, %2;" : "=f"(r.x), "=f"(r.y) : "l"(v));
    return r;
}
static __device__ __forceinline__ unsigned h2u(__half2 h) {
    return *reinterpret_cast<unsigned*>(&h);
}
static __device__ __forceinline__ float2 u2f2(unsigned u) {
    __half2 h = *reinterpret_cast<__half2*>(&u);
    return __half22float2(h);
}

// ---------------- convert fp32 -> fp16 ----------------
__global__ void convert_kernel(const float4* __restrict__ src,
                               __half* __restrict__ dst, long long n4)
{
    long long i = (long long)blockIdx.x * blockDim.x + threadIdx.x;
    if (i < n4) {
        float4 v = src[i];
        uint2 u;
        u.x = h2u(__floats2half2_rn(v.x, v.y));
        u.y = h2u(__floats2half2_rn(v.z, v.w));
        *(uint2*)(dst + i * 4) = u;
    }
}

// ---------------- zero S/deg + (block 0) index dtype detect ----------------
__global__ void zero_detect_kernel(float4* __restrict__ S4, float* __restrict__ deg,
                                   long long nS4, int N,
                                   const unsigned int* __restrict__ w, int nwords)
{
    long long i = (long long)blockIdx.x * blockDim.x + threadIdx.x;
    if (i < nS4) S4[i] = make_float4(0.f, 0.f, 0.f, 0.f);
    long long j = i - nS4;
    if (j >= 0 && j < N) deg[j] = 0.f;

    if (blockIdx.x == 0) {
        __shared__ int any_nonzero;
        if (threadIdx.x == 0) any_nonzero = 0;
        __syncthreads();
        for (int t = threadIdx.x; t < nwords / 2; t += blockDim.x)
            if (w[2 * t + 1] != 0u) any_nonzero = 1;
        __syncthreads();
        if (threadIdx.x == 0) g_idx64 = any_nonzero ? 0 : 1;
    }
}

// ---------------- wmma compute core (shared by both loaders) ----------------
static __device__ __forceinline__ void wmma_mma_and_store(
    int tid, __half* Xs, __half* Ws, float* Cf,
    wmma::fragment<wmma::accumulator, 16, 16, 16, float> (&acc)[2][4])
{
    int w = tid >> 5;
    int warpM = w >> 1, warpN = w & 1;
    #pragma unroll
    for (int ks = 0; ks < CK / 16; ks++) {
        wmma::fragment<wmma::matrix_a, 16, 16, 16, __half, wmma::row_major> af[2];
        wmma::fragment<wmma::matrix_b, 16, 16, 16, __half, wmma::row_major> bf[4];
        #pragma unroll
        for (int i = 0; i < 2; i++)
            wmma::load_matrix_sync(af[i], Xs + (warpM * 32 + i * 16) * LDX + ks * 16, LDX);
        #pragma unroll
        for (int j = 0; j < 4; j++)
            wmma::load_matrix_sync(bf[j], Ws + ks * 16 * LDW + warpN * 64 + j * 16, LDW);
        #pragma unroll
        for (int i = 0; i < 2; i++)
            #pragma unroll
            for (int j = 0; j < 4; j++)
                wmma::mma_sync(acc[i][j], af[i], bf[j], acc[i][j]);
    }
}

// fp16-X pass
__device__ __forceinline__ void wmma_pass_h(
    const __half* __restrict__ Xh, const float* __restrict__ Wf,
    int n0, int N, int tid, __half* Xs, __half* Ws, float* Cf)
{
    int w = tid >> 5;
    int warpM = w >> 1, warpN = w & 1;
    wmma::fragment<wmma::accumulator, 16, 16, 16, float> acc[2][4];
    #pragma unroll
    for (int i = 0; i < 2; i++)
        #pragma unroll
        for (int j = 0; j < 4; j++) wmma::fill_fragment(acc[i][j], 0.f);

    for (int kk = 0; kk < 128; kk += CK) {
        __syncthreads();
        #pragma unroll
        for (int it = 0; it < 4; it++) {
            int idx = tid + it * 256;
            int row = idx >> 3, cq = idx & 7;
            int gr = n0 + row; if (gr > N - 1) gr = N - 1;
            uint4 v = *(const uint4*)(Xh + (size_t)gr * 128 + kk + cq * 8);
            *(uint4*)(Xs + row * LDX + cq * 8) = v;
        }
        #pragma unroll
        for (int it = 0; it < 8; it++) {
            int idx = tid + it * 256;
            int kr = idx >> 5, cq = idx & 31;
            float4 v = *(const float4*)(Wf + (size_t)(kk + kr) * 128 + cq * 4);
            uint2 u;
            u.x = h2u(__floats2half2_rn(v.x, v.y));
            u.y = h2u(__floats2half2_rn(v.z, v.w));
            *(uint2*)(Ws + (size_t)kr * LDW + cq * 4) = u;
        }
        __syncthreads();
        wmma_mma_and_store(tid, Xs, Ws, Cf, acc);
    }
    #pragma unroll
    for (int i = 0; i < 2; i++)
        #pragma unroll
        for (int j = 0; j < 4; j++)
            wmma::store_matrix_sync(Cf + (warpM * 32 + i * 16) * LDC + warpN * 64 + j * 16,
                                    acc[i][j], LDC, wmma::mem_row_major);
    __syncthreads();
}

// fp32-X pass (for S in final)
__device__ __forceinline__ void wmma_pass_f32(
    const float* __restrict__ Xf, const float* __restrict__ Wf,
    int n0, int N, int tid, __half* Xs, __half* Ws, float* Cf)
{
    int w = tid >> 5;
    int warpM = w >> 1, warpN = w & 1;
    wmma::fragment<wmma::accumulator, 16, 16, 16, float> acc[2][4];
    #pragma unroll
    for (int i = 0; i < 2; i++)
        #pragma unroll
        for (int j = 0; j < 4; j++) wmma::fill_fragment(acc[i][j], 0.f);

    for (int kk = 0; kk < 128; kk += CK) {
        __syncthreads();
        #pragma unroll
        for (int it = 0; it < 4; it++) {
            int idx = tid + it * 256;
            int row = idx >> 3, cq = idx & 7;
            int gr = n0 + row; if (gr > N - 1) gr = N - 1;
            const float* sp = Xf + (size_t)gr * 128 + kk + cq * 8;
            float4 v0 = *(const float4*)(sp);
            float4 v1 = *(const float4*)(sp + 4);
            uint4 u;
            u.x = h2u(__floats2half2_rn(v0.x, v0.y));
            u.y = h2u(__floats2half2_rn(v0.z, v0.w));
            u.z = h2u(__floats2half2_rn(v1.x, v1.y));
            u.w = h2u(__floats2half2_rn(v1.z, v1.w));
            *(uint4*)(Xs + row * LDX + cq * 8) = u;
        }
        #pragma unroll
        for (int it = 0; it < 8; it++) {
            int idx = tid + it * 256;
            int kr = idx >> 5, cq = idx & 31;
            float4 v = *(const float4*)(Wf + (size_t)(kk + kr) * 128 + cq * 4);
            uint2 u;
            u.x = h2u(__floats2half2_rn(v.x, v.y));
            u.y = h2u(__floats2half2_rn(v.z, v.w));
            *(uint2*)(Ws + (size_t)kr * LDW + cq * 4) = u;
        }
        __syncthreads();
        wmma_mma_and_store(tid, Xs, Ws, Cf, acc);
    }
    #pragma unroll
    for (int i = 0; i < 2; i++)
        #pragma unroll
        for (int j = 0; j < 4; j++)
            wmma::store_matrix_sync(Cf + (warpM * 32 + i * 16) * LDC + warpN * 64 + j * 16,
                                    acc[i][j], LDC, wmma::mem_row_major);
    __syncthreads();
}

// ---------------- A/B wmma: y=0 -> A (edge_w1 top), y=1 -> B ----------------
__global__ __launch_bounds__(256) void hgemm_ab_kernel(
    const __half* __restrict__ xh, const float* __restrict__ edge_w1,
    __half* __restrict__ A, __half* __restrict__ B, int N)
{
    extern __shared__ char ds[];
    __half* Xs = (__half*)(ds + SMEM_XH);
    __half* Ws = (__half*)(ds + SMEM_WH);
    float*  Cf = (float*)(ds + SMEM_CF);

    int tid = threadIdx.x;
    int n0 = blockIdx.x * 128;
    const float* Wf = blockIdx.y ? (edge_w1 + 128 * 128) : edge_w1;
    __half* Yh = blockIdx.y ? B : A;

    wmma_pass_h(xh, Wf, n0, N, tid, Xs, Ws, Cf);

    int tx = tid & 15, ty = tid >> 4;
    #pragma unroll
    for (int i = 0; i < 8; i++) {
        int row = (i < 4) ? (ty * 4 + i) : (64 + ty * 4 + (i - 4));
        int gr = n0 + row;
        if (gr < N) {
            const float* cr = Cf + row * LDC;
            uint2 u0, u1;
            u0.x = h2u(__floats2half2_rn(cr[tx*4+0], cr[tx*4+1]));
            u0.y = h2u(__floats2half2_rn(cr[tx*4+2], cr[tx*4+3]));
            u1.x = h2u(__floats2half2_rn(cr[64+tx*4+0], cr[64+tx*4+1]));
            u1.y = h2u(__floats2half2_rn(cr[64+tx*4+2], cr[64+tx*4+3]));
            *(uint2*)(Yh + (size_t)gr * 128 + tx * 4)      = u0;
            *(uint2*)(Yh + (size_t)gr * 128 + 64 + tx * 4) = u1;
        }
    }
}

// ---------------- H wmma: Hh = half(relu(LN(xh@node_w1 + b1))) ----------------
__global__ __launch_bounds__(256) void hgemm_h_kernel(
    const __half* __restrict__ xh, const float* __restrict__ node_w1,
    const float* __restrict__ bias, const float* __restrict__ g,
    const float* __restrict__ be, __half* __restrict__ Hh, int N)
{
    extern __shared__ char ds[];
    __half* Xs = (__half*)(ds + SMEM_XH);
    __half* Ws = (__half*)(ds + SMEM_WH);
    float*  Cf = (float*)(ds + SMEM_CF);

    int tid = threadIdx.x;
    int n0 = blockIdx.x * 128;

    wmma_pass_h(xh, node_w1, n0, N, tid, Xs, Ws, Cf);

    int tx = tid & 15, ty = tid >> 4;
    float4 bi0 = *(const float4*)(bias + tx * 4);
    float4 bi1 = *(const float4*)(bias + 64 + tx * 4);
    float4 gg0 = *(const float4*)(g + tx * 4);
    float4 gg1 = *(const float4*)(g + 64 + tx * 4);
    float4 ee0 = *(const float4*)(be + tx * 4);
    float4 ee1 = *(const float4*)(be + 64 + tx * 4);
    #pragma unroll
    for (int i = 0; i < 8; i++) {
        int row = (i < 4) ? (ty * 4 + i) : (64 + ty * 4 + (i - 4));
        int gr = n0 + row;
        const float* cr = Cf + row * LDC;
        float v[8] = { cr[tx*4+0] + bi0.x, cr[tx*4+1] + bi0.y,
                       cr[tx*4+2] + bi0.z, cr[tx*4+3] + bi0.w,
                       cr[64+tx*4+0] + bi1.x, cr[64+tx*4+1] + bi1.y,
                       cr[64+tx*4+2] + bi1.z, cr[64+tx*4+3] + bi1.w };
        float s = 0.f, ss = 0.f;
        #pragma unroll
        for (int j = 0; j < 8; j++) { s += v[j]; ss += v[j] * v[j]; }
        #pragma unroll
        for (int o = 8; o; o >>= 1) {
            s  += __shfl_xor_sync(0xffffffffu, s,  o);
            ss += __shfl_xor_sync(0xffffffffu, ss, o);
        }
        float mean = s * (1.0f / 128.0f);
        float var  = ss * (1.0f / 128.0f) - mean * mean;
        float rs   = rsqrtf(var + 1e-5f);
        float o0 = fmaxf(0.f, (v[0] - mean) * rs * gg0.x + ee0.x);
        float o1 = fmaxf(0.f, (v[1] - mean) * rs * gg0.y + ee0.y);
        float o2 = fmaxf(0.f, (v[2] - mean) * rs * gg0.z + ee0.z);
        float o3 = fmaxf(0.f, (v[3] - mean) * rs * gg0.w + ee0.w);
        float o4 = fmaxf(0.f, (v[4] - mean) * rs * gg1.x + ee1.x);
        float o5 = fmaxf(0.f, (v[5] - mean) * rs * gg1.y + ee1.y);
        float o6 = fmaxf(0.f, (v[6] - mean) * rs * gg1.z + ee1.z);
        float o7 = fmaxf(0.f, (v[7] - mean) * rs * gg1.w + ee1.w);
        if (gr < N) {
            uint2 u0, u1;
            u0.x = h2u(__floats2half2_rn(o0, o1));
            u0.y = h2u(__floats2half2_rn(o2, o3));
            u1.x = h2u(__floats2half2_rn(o4, o5));
            u1.y = h2u(__floats2half2_rn(o6, o7));
            *(uint2*)(Hh + (size_t)gr * 128 + tx * 4)      = u0;
            *(uint2*)(Hh + (size_t)gr * 128 + 64 + tx * 4) = u1;
        }
    }
}

// ---------------- T wmma: T = Hh @ Wnc (fp32 out) ----------------
__global__ __launch_bounds__(256) void hgemm_t_kernel(
    const __half* __restrict__ Hh, float* __restrict__ T, int N)
{
    extern __shared__ char ds[];
    __half* Xs = (__half*)(ds + SMEM_XH);
    __half* Ws = (__half*)(ds + SMEM_WH);
    float*  Cf = (float*)(ds + SMEM_CF);

    int tid = threadIdx.x;
    int n0 = blockIdx.x * 128;

    wmma_pass_h(Hh, g_Wnc, n0, N, tid, Xs, Ws, Cf);

    int tx = tid & 15, ty = tid >> 4;
    #pragma unroll
    for (int i = 0; i < 8; i++) {
        int row = (i < 4) ? (ty * 4 + i) : (64 + ty * 4 + (i - 4));
        int gr = n0 + row;
        if (gr < N) {
            const float* cr = Cf + row * LDC;
            *(float4*)(T + (size_t)gr * 128 + tx * 4) =
                make_float4(cr[tx*4+0], cr[tx*4+1], cr[tx*4+2], cr[tx*4+3]);
            *(float4*)(T + (size_t)gr * 128 + 64 + tx * 4) =
                make_float4(cr[64+tx*4+0], cr[64+tx*4+1], cr[64+tx*4+2], cr[64+tx*4+3]);
        }
    }
}

// ---------------- wmma final: out = LN(S@Wec + T + x + cbias + deg*evec) ----------------
__global__ __launch_bounds__(256) void final_wmma_kernel(
    const float* __restrict__ S, const float* __restrict__ T,
    const float* __restrict__ x, const float* __restrict__ deg,
    const float* __restrict__ lng, const float* __restrict__ lnb,
    float* __restrict__ Y, int N)
{
    extern __shared__ char ds[];
    __half* Xs = (__half*)(ds + SMEM_XH);
    __half* Ws = (__half*)(ds + SMEM_WH);
    float*  Cf = (float*)(ds + SMEM_CF);

    int tid = threadIdx.x;
    int n0 = blockIdx.x * 128;

    wmma_pass_f32(S, g_Wec, n0, N, tid, Xs, Ws, Cf);

    int tx = tid & 15, ty = tid >> 4;
    float4 cb0 = *(const float4*)(g_cbias + tx * 4);
    float4 cb1 = *(const float4*)(g_cbias + 64 + tx * 4);
    float4 ev0 = *(const float4*)(g_evec + tx * 4);
    float4 ev1 = *(const float4*)(g_evec + 64 + tx * 4);
    float4 gg0 = *(const float4*)(lng + tx * 4);
    float4 gg1 = *(const float4*)(lng + 64 + tx * 4);
    float4 bb0 = *(const float4*)(lnb + tx * 4);
    float4 bb1 = *(const float4*)(lnb + 64 + tx * 4);

    #pragma unroll
    for (int i = 0; i < 8; i++) {
        int row = (i < 4) ? (ty * 4 + i) : (64 + ty * 4 + (i - 4));
        int gr = n0 + row;
        int gl = (gr > N - 1) ? (N - 1) : gr;
        float d = deg[gl];
        float4 xr0 = *(const float4*)(x + (size_t)gl * 128 + tx * 4);
        float4 xr1 = *(const float4*)(x + (size_t)gl * 128 + 64 + tx * 4);
        float4 tr0 = *(const float4*)(T + (size_t)gl * 128 + tx * 4);
        float4 tr1 = *(const float4*)(T + (size_t)gl * 128 + 64 + tx * 4);
        const float* cr = Cf + row * LDC;
        float v[8];
        v[0] = cr[tx*4+0] + tr0.x + xr0.x + cb0.x + d * ev0.x;
        v[1] = cr[tx*4+1] + tr0.y + xr0.y + cb0.y + d * ev0.y;
        v[2] = cr[tx*4+2] + tr0.z + xr0.z + cb0.z + d * ev0.z;
        v[3] = cr[tx*4+3] + tr0.w + xr0.w + cb0.w + d * ev0.w;
        v[4] = cr[64+tx*4+0] + tr1.x + xr1.x + cb1.x + d * ev1.x;
        v[5] = cr[64+tx*4+1] + tr1.y + xr1.y + cb1.y + d * ev1.y;
        v[6] = cr[64+tx*4+2] + tr1.z + xr1.z + cb1.z + d * ev1.z;
        v[7] = cr[64+tx*4+3] + tr1.w + xr1.w + cb1.w + d * ev1.w;
        float s = 0.f, ss = 0.f;
        #pragma unroll
        for (int j = 0; j < 8; j++) { s += v[j]; ss += v[j] * v[j]; }
        #pragma unroll
        for (int o = 8; o; o >>= 1) {
            s  += __shfl_xor_sync(0xffffffffu, s,  o);
            ss += __shfl_xor_sync(0xffffffffu, ss, o);
        }
        float mean = s * (1.0f / 128.0f);
        float var  = ss * (1.0f / 128.0f) - mean * mean;
        float rs   = rsqrtf(var + 1e-5f);
        float o0 = (v[0] - mean) * rs * gg0.x + bb0.x;
        float o1 = (v[1] - mean) * rs * gg0.y + bb0.y;
        float o2 = (v[2] - mean) * rs * gg0.z + bb0.z;
        float o3 = (v[3] - mean) * rs * gg0.w + bb0.w;
        float o4 = (v[4] - mean) * rs * gg1.x + bb1.x;
        float o5 = (v[5] - mean) * rs * gg1.y + bb1.y;
        float o6 = (v[6] - mean) * rs * gg1.z + bb1.z;
        float o7 = (v[7] - mean) * rs * gg1.w + bb1.w;
        if (gr < N) {
            *(float4*)(Y + (size_t)gr * 128 + tx * 4)      = make_float4(o0, o1, o2, o3);
            *(float4*)(Y + (size_t)gr * 128 + 64 + tx * 4) = make_float4(o4, o5, o6, o7);
        }
    }
}

// ---------------- FFMA GEMM inner pass (prep only) ----------------
__device__ __forceinline__ void gemm_pass(
    const float* __restrict__ X, const float* __restrict__ W,
    int n0, int N, int tid, int tx, int ty,
    float* Xs2, float* Ws, unsigned long long (&acc)[8][4])
{
    for (int kk = 0; kk < 128; kk += BK) {
        __syncthreads();
        #pragma unroll
        for (int i = 0; i < 4; i++) {
            int idx = tid + i * 256;
            int row = idx >> 3, q = idx & 7;
            int gr = n0 + row; if (gr > N - 1) gr = N - 1;
            float4 v = *(const float4*)(X + (size_t)gr * 128 + kk + q * 4);
            float* s = Xs2 + row * 64 + q * 8;
            *(float4*)(s)     = make_float4(v.x, v.x, v.y, v.y);
            *(float4*)(s + 4) = make_float4(v.z, v.z, v.w, v.w);
        }
        #pragma unroll
        for (int i = 0; i < 4; i++) {
            int idx = tid + i * 256;
            int kr = idx >> 5, cq = idx & 31;
            float4 v = *(const float4*)(W + (size_t)(kk + kr) * 128 + cq * 4);
            *(float4*)(Ws + kr * 128 + cq * 4) = v;
        }
        __syncthreads();
        #pragma unroll
        for (int k = 0; k < BK; k++) {
            float4 b0 = *(const float4*)(Ws + k * 128 + tx * 4);
            float4 b1 = *(const float4*)(Ws + k * 128 + 64 + tx * 4);
            unsigned long long bp[4];
            bp[0] = pack2(b0.x, b0.y); bp[1] = pack2(b0.z, b0.w);
            bp[2] = pack2(b1.x, b1.y); bp[3] = pack2(b1.z, b1.w);
            #pragma unroll
            for (int i = 0; i < 8; i++) {
                int row = (i < 4) ? (ty * 4 + i) : (64 + ty * 4 + (i - 4));
                unsigned long long a2 =
                    *(const unsigned long long*)(Xs2 + row * 64 + k * 2);
                fma2(acc[i][0], a2, bp[0]);
                fma2(acc[i][1], a2, bp[1]);
                fma2(acc[i][2], a2, bp[2]);
                fma2(acc[i][3], a2, bp[3]);
            }
        }
    }
}

// ---------------- edge kernel (R12 low-reg ILP-2) ----------------
__global__ __launch_bounds__(256, 5) void edge_kernel(
    const __half* __restrict__ A, const __half* __restrict__ B,
    const float* __restrict__ ea, const void* __restrict__ ei_raw,
    const float* __restrict__ W5, const float* __restrict__ eb1,
    const float* __restrict__ g1, const float* __restrict__ be1,
    float* __restrict__ S, float* __restrict__ deg, int E, int N)
{
    __shared__ float sW5[5 * 128];
    __shared__ float sb[128], sg[128], sbe[128];
    int tid = threadIdx.x;
    for (int i = tid; i < 5 * 128; i += 256) sW5[i] = W5[i];
    if (tid < 128) { sb[tid] = eb1[tid]; sg[tid] = g1[tid]; sbe[tid] = be1[tid]; }
    __syncthreads();

    int lane = tid & 31;
    int gw = (blockIdx.x * 256 + tid) >> 5;
    int nw = (gridDim.x * 256) >> 5;
    int idx64 = g_idx64;
    int c = lane * 4;

    for (long long e0 = 2LL * gw; e0 < E; e0 += 2LL * nw) {
        long long e1 = e0 + 1;
        bool valid1 = (e1 < E);

        int src0, dst0, src1, dst1;
        if (idx64) {
            const long long* ei = (const long long*)ei_raw;
            src0 = (int)ei[e0];
            dst0 = (int)ei[(long long)E + e0];
            src1 = valid1 ? (int)ei[e1] : src0;
            dst1 = valid1 ? (int)ei[(long long)E + e1] : dst0;
        } else {
            const int* ei = (const int*)ei_raw;
            src0 = ei[e0];
            dst0 = ei[(long long)E + e0];
            src1 = valid1 ? ei[e1] : src0;
            dst1 = valid1 ? ei[(long long)E + e1] : dst0;
        }
        src0 = min(max(src0, 0), N - 1); dst0 = min(max(dst0, 0), N - 1);
        src1 = min(max(src1, 0), N - 1); dst1 = min(max(dst1, 0), N - 1);

        uint2 ra0 = __ldg((const uint2*)(A + (size_t)src0 * 128 + c));
        uint2 rb0 = __ldg((const uint2*)(B + (size_t)dst0 * 128 + c));
        uint2 ra1 = __ldg((const uint2*)(A + (size_t)src1 * 128 + c));
        uint2 rb1 = __ldg((const uint2*)(B + (size_t)dst1 * 128 + c));

        const float* eap0 = ea + e0 * 5;
        const float* eap1 = ea + (valid1 ? e1 : e0) * 5;
        float e00 = eap0[0], e01 = eap0[1], e02 = eap0[2], e03 = eap0[3], e04 = eap0[4];
        float e10 = eap1[0], e11 = eap1[1], e12 = eap1[2], e13 = eap1[3], e14 = eap1[4];

        float4 w0 = *(const float4*)(sW5 + 0 * 128 + c);
        float4 w1 = *(const float4*)(sW5 + 1 * 128 + c);
        float4 w2 = *(const float4*)(sW5 + 2 * 128 + c);
        float4 w3 = *(const float4*)(sW5 + 3 * 128 + c);
        float4 w4 = *(const float4*)(sW5 + 4 * 128 + c);
        float4 sb4 = *(const float4*)(sb + c);

        float b00 = sb4.x + e00 * w0.x + e01 * w1.x + e02 * w2.x + e03 * w3.x + e04 * w4.x;
        float b01 = sb4.y + e00 * w0.y + e01 * w1.y + e02 * w2.y + e03 * w3.y + e04 * w4.y;
        float b02 = sb4.z + e00 * w0.z + e01 * w1.z + e02 * w2.z + e03 * w3.z + e04 * w4.z;
        float b03 = sb4.w + e00 * w0.w + e01 * w1.w + e02 * w2.w + e03 * w3.w + e04 * w4.w;
        float b10 = sb4.x + e10 * w0.x + e11 * w1.x + e12 * w2.x + e13 * w3.x + e14 * w4.x;
        float b11 = sb4.y + e10 * w0.y + e11 * w1.y + e12 * w2.y + e13 * w3.y + e14 * w4.y;
        float b12 = sb4.z + e10 * w0.z + e11 * w1.z + e12 * w2.z + e13 * w3.z + e14 * w4.z;
        float b13 = sb4.w + e10 * w0.w + e11 * w1.w + e12 * w2.w + e13 * w3.w + e14 * w4.w;

        float2 a0lo = u2f2(ra0.x), a0hi = u2f2(ra0.y);
        float2 b0lo = u2f2(rb0.x), b0hi = u2f2(rb0.y);
        float2 a1lo = u2f2(ra1.x), a1hi = u2f2(ra1.y);
        float2 b1lo = u2f2(rb1.x), b1hi = u2f2(rb1.y);

        float p00 = a0lo.x + b0lo.x + b00;
        float p01 = a0lo.y + b0lo.y + b01;
        float p02 = a0hi.x + b0hi.x + b02;
        float p03 = a0hi.y + b0hi.y + b03;
        float p10 = a1lo.x + b1lo.x + b10;
        float p11 = a1lo.y + b1lo.y + b11;
        float p12 = a1hi.x + b1hi.x + b12;
        float p13 = a1hi.y + b1hi.y + b13;

        float s0 = p00 + p01 + p02 + p03;
        float q0 = p00 * p00 + p01 * p01 + p02 * p02 + p03 * p03;
        float s1 = p10 + p11 + p12 + p13;
        float q1 = p10 * p10 + p11 * p11 + p12 * p12 + p13 * p13;
        #pragma unroll
        for (int o = 16; o; o >>= 1) {
            s0 += __shfl_xor_sync(0xffffffffu, s0, o);
            q0 += __shfl_xor_sync(0xffffffffu, q0, o);
            s1 += __shfl_xor_sync(0xffffffffu, s1, o);
            q1 += __shfl_xor_sync(0xffffffffu, q1, o);
        }
        float mean0 = s0 * (1.0f / 128.0f);
        float rs0   = rsqrtf(q0 * (1.0f / 128.0f) - mean0 * mean0 + 1e-5f);
        float mean1 = s1 * (1.0f / 128.0f);
        float rs1   = rsqrtf(q1 * (1.0f / 128.0f) - mean1 * mean1 + 1e-5f);

        float4 sg4 = *(const float4*)(sg + c);
        float4 se4 = *(const float4*)(sbe + c);

        float v00 = fmaxf(0.f, (p00 - mean0) * rs0 * sg4.x + se4.x);
        float v01 = fmaxf(0.f, (p01 - mean0) * rs0 * sg4.y + se4.y);
        float v02 = fmaxf(0.f, (p02 - mean0) * rs0 * sg4.z + se4.z);
        float v03 = fmaxf(0.f, (p03 - mean0) * rs0 * sg4.w + se4.w);

        float* dp0 = S + (size_t)dst0 * 128 + c;
        asm volatile("red.global.add.v4.f32 [%0], {%1,%2,%3,%4};"
                     :: "l"(dp0), "f"(v00), "f"(v01), "f"(v02), "f"(v03) : "memory");

        if (valid1) {
            float v10 = fmaxf(0.f, (p10 - mean1) * rs1 * sg4.x + se4.x);
            float v11 = fmaxf(0.f, (p11 - mean1) * rs1 * sg4.y + se4.y);
            float v12 = fmaxf(0.f, (p12 - mean1) * rs1 * sg4.z + se4.z);
            float v13 = fmaxf(0.f, (p13 - mean1) * rs1 * sg4.w + se4.w);
            float* dp1 = S + (size_t)dst1 * 128 + c;
            asm volatile("red.global.add.v4.f32 [%0], {%1,%2,%3,%4};"
                         :: "l"(dp1), "f"(v10), "f"(v11), "f"(v12), "f"(v13) : "memory");
        }
        if (lane == 0) atomicAdd(deg + dst0, 1.0f);
        if (lane == 1 && valid1) atomicAdd(deg + dst1, 1.0f);
    }
}

// ---------------- prep kernel ----------------
__global__ __launch_bounds__(256, 2) void prep_kernel(
    const float* __restrict__ w2n, const float* __restrict__ w2e,
    const float* __restrict__ U,
    const float* __restrict__ bn2, const float* __restrict__ be2,
    const float* __restrict__ ub,
    float* __restrict__ Wnc, float* __restrict__ Wec,
    float* __restrict__ cb, float* __restrict__ ev)
{
    __shared__ float Xs2[128 * 64];
    __shared__ float Ws[BK * 128];
    int tid = threadIdx.x, tx = tid & 15, ty = tid >> 4;
    int y = blockIdx.y;

    if (y == 2) {
        int j = tid & 127, h = tid >> 7;
        float a = 0.f, b = 0.f;
        int m0 = h * 64;
        #pragma unroll 16
        for (int m = m0; m < m0 + 64; m++) {
            a += bn2[m] * U[m * 128 + j];
            b += be2[m] * U[(128 + m) * 128 + j];
        }
        Xs2[tid] = a;
        Xs2[512 + tid] = b;
        __syncthreads();
        if (h == 0) {
            cb[j] = Xs2[j] + Xs2[128 + j] + ub[j];
            ev[j] = Xs2[512 + j] + Xs2[640 + j];
        }
        return;
    }

    const float* X = y ? w2e : w2n;
    const float* W = y ? (U + 128 * 128) : U;
    float* out = y ? Wec : Wnc;

    unsigned long long acc[8][4];
    #pragma unroll
    for (int i = 0; i < 8; i++)
        #pragma unroll
        for (int p = 0; p < 4; p++) acc[i][p] = 0ULL;

    gemm_pass(X, W, 0, 128, tid, tx, ty, Xs2, Ws, acc);

    #pragma unroll
    for (int i = 0; i < 8; i++) {
        int row = (i < 4) ? (ty * 4 + i) : (64 + ty * 4 + (i - 4));
        float2 f0 = unpack2(acc[i][0]), f1 = unpack2(acc[i][1]);
        float2 f2 = unpack2(acc[i][2]), f3 = unpack2(acc[i][3]);
        *(float4*)(out + (size_t)row * 128 + tx * 4)      = make_float4(f0.x, f0.y, f1.x, f1.y);
        *(float4*)(out + (size_t)row * 128 + 64 + tx * 4) = make_float4(f2.x, f2.y, f3.x, f3.y);
    }
}

// ---------------- launch ----------------
extern "C" void kernel_launch(void* const* d_in, const int* in_sizes, int n_in,
                              void* d_out, int out_size)
{
    const float* x         = (const float*)d_in[0];
    const float* edge_attr = (const float*)d_in[1];
    const float* node_w1   = (const float*)d_in[3];
    const float* node_b1   = (const float*)d_in[4];
    const float* node_g1   = (const float*)d_in[5];
    const float* node_be1  = (const float*)d_in[6];
    const float* node_w2   = (const float*)d_in[7];
    const float* node_b2   = (const float*)d_in[8];
    const float* edge_w1   = (const float*)d_in[9];
    const float* edge_b1   = (const float*)d_in[10];
    const float* edge_g1   = (const float*)d_in[11];
    const float* edge_be1  = (const float*)d_in[12];
    const float* edge_w2   = (const float*)d_in[13];
    const float* edge_b2   = (const float*)d_in[14];
    const float* upd_w     = (const float*)d_in[15];
    const float* upd_b     = (const float*)d_in[16];
    const float* ln_g      = (const float*)d_in[17];
    const float* ln_b      = (const float*)d_in[18];
    const void*  ei        = d_in[19];
    float* out = (float*)d_out;

    int N = in_sizes[0] / 128;
    int E = in_sizes[19] / 2;

    float *pS, *pT, *pdeg, *pWnc, *pWec, *pcb, *pev;
    __half *pA, *pB, *pxh, *pHh;
    cudaGetSymbolAddress((void**)&pxh,  g_xh);
    cudaGetSymbolAddress((void**)&pHh,  g_Hh);
    cudaGetSymbolAddress((void**)&pA,   g_A);
    cudaGetSymbolAddress((void**)&pB,   g_B);
    cudaGetSymbolAddress((void**)&pS,   g_S);
    cudaGetSymbolAddress((void**)&pT,   g_T);
    cudaGetSymbolAddress((void**)&pdeg, g_deg);
    cudaGetSymbolAddress((void**)&pWnc, g_Wnc);
    cudaGetSymbolAddress((void**)&pWec, g_Wec);
    cudaGetSymbolAddress((void**)&pcb,  g_cbias);
    cudaGetSymbolAddress((void**)&pev,  g_evec);

    static cudaStream_t s1 = 0;
    static cudaEvent_t eFork = 0, eZero = 0, eAB = 0, eJoin = 0;
    static bool attrSet = false;
    if (!s1) cudaStreamCreateWithFlags(&s1, cudaStreamNonBlocking);
    if (!eFork) cudaEventCreateWithFlags(&eFork, cudaEventDisableTiming);
    if (!eZero) cudaEventCreateWithFlags(&eZero, cudaEventDisableTiming);
    if (!eAB) cudaEventCreateWithFlags(&eAB, cudaEventDisableTiming);
    if (!eJoin) cudaEventCreateWithFlags(&eJoin, cudaEventDisableTiming);
    if (!attrSet) {
        cudaFuncSetAttribute(hgemm_ab_kernel,
                             cudaFuncAttributeMaxDynamicSharedMemorySize, HGEMM_SMEM);
        cudaFuncSetAttribute(hgemm_h_kernel,
                             cudaFuncAttributeMaxDynamicSharedMemorySize, HGEMM_SMEM);
        cudaFuncSetAttribute(hgemm_t_kernel,
                             cudaFuncAttributeMaxDynamicSharedMemorySize, HGEMM_SMEM);
        cudaFuncSetAttribute(final_wmma_kernel,
                             cudaFuncAttributeMaxDynamicSharedMemorySize, HGEMM_SMEM);
        attrSet = true;
    }

    cudaStream_t s0 = cudaStreamLegacy;
    {
        cudaStreamCaptureStatus st = cudaStreamCaptureStatusNone;
        if (cudaStreamIsCapturing(cudaStreamLegacy, &st) == cudaSuccess &&
            st == cudaStreamCaptureStatusActive) {
            s0 = cudaStreamLegacy;
        } else {
            cudaStreamCaptureStatus st2 = cudaStreamCaptureStatusNone;
            if (cudaStreamIsCapturing(cudaStreamPerThread, &st2) == cudaSuccess &&
                st2 == cudaStreamCaptureStatusActive) {
                s0 = cudaStreamPerThread;
            }
        }
    }

    int gb = (N + 127) / 128;
    int nwords = 2 * E; if (nwords > 1024) nwords = 1024;
    long long nS4 = (long long)N * 32;
    long long ztot = nS4 + N;
    long long nx4 = (long long)N * 32;

    // fork
    cudaEventRecord(eFork, s0);
    cudaStreamWaitEvent(s1, eFork, 0);

    // s0: x -> fp16 (single pass; feeds 3 GEMMs)
    convert_kernel<<<(unsigned)((nx4 + 255) / 256), 256, 0, s0>>>(
        (const float4*)x, pxh, nx4);

    // s0: A,B via wmma (fp16 loaders)
    hgemm_ab_kernel<<<dim3(gb, 2), 256, HGEMM_SMEM, s0>>>(pxh, edge_w1, pA, pB, N);
    cudaEventRecord(eAB, s0);

    // s1: zero S/deg + dtype detect
    zero_detect_kernel<<<(unsigned)((ztot + 255) / 256), 256, 0, s1>>>(
        (float4*)pS, pdeg, nS4, N, (const unsigned int*)ei, nwords);
    cudaEventRecord(eZero, s1);

    // s1: prep (weight folding)
    prep_kernel<<<dim3(1, 3), 256, 0, s1>>>(node_w2, edge_w2, upd_w,
                                            node_b2, edge_b2, upd_b,
                                            pWnc, pWec, pcb, pev);

    // s1: H (fp16 out) then T (wmma), after AB clears the head
    cudaStreamWaitEvent(s1, eAB, 0);
    hgemm_h_kernel<<<gb, 256, HGEMM_SMEM, s1>>>(pxh, node_w1,
                                                node_b1, node_g1, node_be1, pHh, N);
    hgemm_t_kernel<<<gb, 256, HGEMM_SMEM, s1>>>(pHh, pT, N);

    // s0: edge pipeline (waits zero)
    cudaStreamWaitEvent(s0, eZero, 0);
    edge_kernel<<<740, 256, 0, s0>>>(pA, pB, edge_attr, ei,
                                     edge_w1 + 256 * 128, edge_b1, edge_g1, edge_be1,
                                     pS, pdeg, E, N);

    // join
    cudaEventRecord(eJoin, s1);
    cudaStreamWaitEvent(s0, eJoin, 0);

    // s0: final via wmma (S fp32 in-loader convert; S read exactly once)
    final_wmma_kernel<<<gb, 256, HGEMM_SMEM, s0>>>(pS, pT, x, pdeg, ln_g, ln_b, out, N);
}